// round 16
// baseline (speedup 1.0000x reference)
#include <cuda_runtime.h>
#include <cstdint>

// ---------------------------------------------------------------------------
// GIN: 3 layers of { rst = h + segment_sum(h[src], dst); h = MLP2(rst) }
// N=100000, E=1600000, D=128.
//   - CSR build: hist, scan_reduce, scan_final (bsum merged in), fill
//   - k_agg: plain gather (warp/node, float4/lane) - at L2 BW cap
//   - k_mlp: fused 2-GEMM FFMA2 MLP, TILE_M=88, 352 thr, 2 blocks/SM
//     (3.84 waves vs 5.28 -> tail quantization 13.5% -> 4%)
//   - last layer folded to single GEMM: W12 = W1@W2, b12 = b1@W2 + b2
// ---------------------------------------------------------------------------

#define DIM 128
#define MAXN 100000
#define MAXE 1600000
#define TILE_M 88
#define SA_PITCH 132
#define MLP_THREADS 352
#define MLP_SMEM_BYTES ((128 * 128 + TILE_M * SA_PITCH) * 4)   // 112000
#define SCAN_CHUNK 2048
#define MAX_SCAN_BLOCKS 64

typedef unsigned long long u64;

// scratch (device globals; zero-initialized at load; k_fill re-zeros g_deg)
__device__ int   g_deg[MAXN];
__device__ int   g_rowptr[MAXN + 1];
__device__ int   g_cursor[MAXN];
__device__ int   g_col[MAXE];
__device__ int   g_bsum[MAX_SCAN_BLOCKS];
__device__ __align__(16) float g_rst[(size_t)MAXN * DIM];
__device__ __align__(16) float g_hA [(size_t)MAXN * DIM];
__device__ __align__(16) float g_hB [(size_t)MAXN * DIM];
__device__ __align__(16) float g_W12[DIM * DIM];
__device__ __align__(16) float g_b12[DIM];

// ------------------------- f32x2 helpers ------------------------------------

__device__ __forceinline__ u64 pack2(float x, float y) {
    u64 r;
    asm("mov.b64 %0, {%1, %2};" : "=l"(r) : "f"(x), "f"(y));
    return r;
}
__device__ __forceinline__ void unpack2(u64 v, float& x, float& y) {
    asm("mov.b64 {%0, %1}, %2;" : "=f"(x), "=f"(y) : "l"(v));
}
__device__ __forceinline__ void fma2(u64& d, u64 a, u64 b) {
    asm("fma.rn.f32x2 %0, %1, %2, %0;" : "+l"(d) : "l"(a), "l"(b));
}

// -------------------------- CSR build ---------------------------------------

__global__ void k_hist(const int* __restrict__ dst, int e) {
    int i = blockIdx.x * blockDim.x + threadIdx.x;
    if (i < e) atomicAdd(&g_deg[dst[i]], 1);
}

__global__ void k_scan_reduce(int n) {
    __shared__ int s[256];
    int tid = threadIdx.x;
    int base = blockIdx.x * SCAN_CHUNK + tid * 8;
    int tot = 0;
#pragma unroll
    for (int j = 0; j < 8; ++j) {
        int idx = base + j;
        tot += (idx < n) ? g_deg[idx] : 0;
    }
    s[tid] = tot;
    __syncthreads();
    for (int off = 128; off > 0; off >>= 1) {
        if (tid < off) s[tid] += s[tid + off];
        __syncthreads();
    }
    if (tid == 0) g_bsum[blockIdx.x] = s[0];
}

// full exclusive scan; computes own chunk base from g_bsum totals (bsum merged)
__global__ void k_scan_final(int n, int e, int nb) {
    __shared__ int s[256];
    int tid = threadIdx.x;
    // chunk base: sum of totals of preceding chunks (small, L2-cached)
    int cbase = 0;
    for (int b = 0; b < blockIdx.x; ++b) cbase += g_bsum[b];
    int base = blockIdx.x * SCAN_CHUNK + tid * 8;
    int v[8];
    int run = 0;
#pragma unroll
    for (int j = 0; j < 8; ++j) {
        int idx = base + j;
        int t = (idx < n) ? g_deg[idx] : 0;
        v[j] = run;
        run += t;
    }
    int tot = run;
    s[tid] = tot;
    __syncthreads();
    for (int off = 1; off < 256; off <<= 1) {
        int add = (tid >= off) ? s[tid - off] : 0;
        __syncthreads();
        s[tid] += add;
        __syncthreads();
    }
    int texcl = s[tid] - tot;
    int pref = cbase + texcl;
#pragma unroll
    for (int j = 0; j < 8; ++j) {
        int idx = base + j;
        if (idx < n) {
            int r = pref + v[j];
            g_rowptr[idx] = r;
            g_cursor[idx] = r;
        }
    }
    if (blockIdx.x == 0 && tid == 0) g_rowptr[n] = e;
}

// bucket fill; re-zeroes g_deg for the next graph replay
__global__ void k_fill(const int* __restrict__ src, const int* __restrict__ dst,
                       int e, int n) {
    int i = blockIdx.x * blockDim.x + threadIdx.x;
    if (i < n) g_deg[i] = 0;
    if (i < e) {
        int d = dst[i];
        int pos = atomicAdd(&g_cursor[d], 1);
        g_col[pos] = src[i];
    }
}

// -------------------- last-layer weight folding ------------------------------

__global__ void k_wbfuse(const float* __restrict__ W1g, const float* __restrict__ W2g,
                         const float* __restrict__ b1g, const float* __restrict__ b2g) {
    __shared__ float row[128];
    int nn = threadIdx.x;
    if (blockIdx.x < 128) {
        int k = blockIdx.x;
        row[nn] = W1g[k * 128 + nn];
        __syncthreads();
        float acc = 0.f;
#pragma unroll 8
        for (int j = 0; j < 128; ++j) acc += row[j] * W2g[j * 128 + nn];
        g_W12[k * 128 + nn] = acc;
    } else {
        row[nn] = b1g[nn];
        __syncthreads();
        float acc = b2g[nn];
#pragma unroll 8
        for (int j = 0; j < 128; ++j) acc += row[j] * W2g[j * 128 + nn];
        g_b12[nn] = acc;
    }
}

// ---------------------- aggregation (L2-cap-proven) --------------------------
// warp per node, lane owns one float4 of the 128-dim row. EPS = 0.

__global__ void __launch_bounds__(256) k_agg(const float* __restrict__ hin,
                                             float* __restrict__ rst, int n) {
    int warp = (blockIdx.x * blockDim.x + threadIdx.x) >> 5;
    int lane = threadIdx.x & 31;
    if (warp >= n) return;
    const float4* __restrict__ h4 = (const float4*)hin;
    float4 a = h4[(size_t)warp * 32 + lane];  // self, (1+eps)=1
    int s = g_rowptr[warp];
    int epos = g_rowptr[warp + 1];
    for (int i = s; i < epos; ++i) {
        int sn = g_col[i];
        float4 v = __ldg(&h4[(size_t)sn * 32 + lane]);
        a.x += v.x; a.y += v.y; a.z += v.z; a.w += v.w;
    }
    ((float4*)rst)[(size_t)warp * 32 + lane] = a;
}

// ---------------------- fused 2-GEMM MLP (FFMA2) -----------------------------
// out = relu( relu(A @ W1 + b1) @ W2 + b2 ).  352 threads, TILE 88,
// micro-tile 8 rows x 4 cols, packed f32x2 accumulators, 2 blocks/SM.

__global__ void __launch_bounds__(MLP_THREADS, 2)
k_mlp(const float* __restrict__ A,
      const float* __restrict__ W1, const float* __restrict__ b1,
      const float* __restrict__ W2, const float* __restrict__ b2,
      float* __restrict__ out, int n) {
    extern __shared__ float smem[];
    float* sW = smem;                 // 128*128
    float* sA = sW + 128 * 128;       // 88*SA_PITCH

    const int tid  = threadIdx.x;
    const int row0 = blockIdx.x * TILE_M;

    {
        const float4* w4 = (const float4*)W1;
        float4* s4 = (float4*)sW;
#pragma unroll
        for (int it = 0; it < 12; ++it) {
            int idx = tid + it * MLP_THREADS;
            if (idx < 4096) s4[idx] = w4[idx];
        }
    }
    {
#pragma unroll
        for (int it = 0; it < 8; ++it) {
            int idx = tid + it * MLP_THREADS;    // 0..2815
            int r   = idx >> 5;
            int kq  = idx & 31;
            int rg  = row0 + r;
            float4 f = (rg < n) ? ((const float4*)A)[(size_t)rg * 32 + kq]
                                : make_float4(0.f, 0.f, 0.f, 0.f);
            *(float4*)&sA[r * SA_PITCH + kq * 4] = f;
        }
    }
    __syncthreads();

    const int trow = tid >> 5;   // 0..10 -> rows trow*8..+7
    const int tcol = tid & 31;   // 0..31 -> cols tcol*4..+3
    const int r0   = trow * 8;
    const int c0   = tcol * 4;

    u64 acc[8][2];

    // ---- phase 1: h1 = relu(A @ W1 + b1) ----
    {
        u64 bb0 = pack2(b1[c0],     b1[c0 + 1]);
        u64 bb1 = pack2(b1[c0 + 2], b1[c0 + 3]);
#pragma unroll
        for (int i = 0; i < 8; ++i) { acc[i][0] = bb0; acc[i][1] = bb1; }
    }
#pragma unroll 1
    for (int k0 = 0; k0 < 128; k0 += 4) {
        float4 a4[8];
#pragma unroll
        for (int i = 0; i < 8; ++i)
            a4[i] = *(const float4*)&sA[(r0 + i) * SA_PITCH + k0];
#pragma unroll
        for (int kk = 0; kk < 4; ++kk) {
            ulonglong2 w = *(const ulonglong2*)&sW[(k0 + kk) * 128 + c0];
#pragma unroll
            for (int i = 0; i < 8; ++i) {
                float av = ((const float*)&a4[i])[kk];
                u64 aa = pack2(av, av);
                fma2(acc[i][0], aa, w.x);
                fma2(acc[i][1], aa, w.y);
            }
        }
    }
    __syncthreads();

    // h1 -> sA (relu), W2 -> sW
#pragma unroll
    for (int i = 0; i < 8; ++i) {
#pragma unroll
        for (int p = 0; p < 2; ++p) {
            float x, y;
            unpack2(acc[i][p], x, y);
            x = fmaxf(x, 0.f); y = fmaxf(y, 0.f);
            *(u64*)&sA[(r0 + i) * SA_PITCH + c0 + 2 * p] = pack2(x, y);
        }
    }
    {
        const float4* w4 = (const float4*)W2;
        float4* s4 = (float4*)sW;
#pragma unroll
        for (int it = 0; it < 12; ++it) {
            int idx = tid + it * MLP_THREADS;
            if (idx < 4096) s4[idx] = w4[idx];
        }
    }
    __syncthreads();

    // ---- phase 2: out = relu(h1 @ W2 + b2) ----
    {
        u64 bb0 = pack2(b2[c0],     b2[c0 + 1]);
        u64 bb1 = pack2(b2[c0 + 2], b2[c0 + 3]);
#pragma unroll
        for (int i = 0; i < 8; ++i) { acc[i][0] = bb0; acc[i][1] = bb1; }
    }
#pragma unroll 1
    for (int k0 = 0; k0 < 128; k0 += 4) {
        float4 a4[8];
#pragma unroll
        for (int i = 0; i < 8; ++i)
            a4[i] = *(const float4*)&sA[(r0 + i) * SA_PITCH + k0];
#pragma unroll
        for (int kk = 0; kk < 4; ++kk) {
            ulonglong2 w = *(const ulonglong2*)&sW[(k0 + kk) * 128 + c0];
#pragma unroll
            for (int i = 0; i < 8; ++i) {
                float av = ((const float*)&a4[i])[kk];
                u64 aa = pack2(av, av);
                fma2(acc[i][0], aa, w.x);
                fma2(acc[i][1], aa, w.y);
            }
        }
    }

#pragma unroll
    for (int i = 0; i < 8; ++i) {
        int rg = row0 + r0 + i;
        if (rg < n) {
            float x0, y0, x1, y1;
            unpack2(acc[i][0], x0, y0);
            unpack2(acc[i][1], x1, y1);
            x0 = fmaxf(x0, 0.f); y0 = fmaxf(y0, 0.f);
            x1 = fmaxf(x1, 0.f); y1 = fmaxf(y1, 0.f);
            ((float4*)out)[(size_t)rg * 32 + tcol] = make_float4(x0, y0, x1, y1);
        }
    }
}

// ---------------------- last layer: single folded GEMM -----------------------
// out = A @ W12 + b12  (no relu)

__global__ void __launch_bounds__(MLP_THREADS, 2)
k_mlp1(const float* __restrict__ A, float* __restrict__ out, int n) {
    extern __shared__ float smem[];
    float* sW = smem;
    float* sA = sW + 128 * 128;

    const int tid  = threadIdx.x;
    const int row0 = blockIdx.x * TILE_M;

    {
        const float4* w4 = (const float4*)g_W12;
        float4* s4 = (float4*)sW;
#pragma unroll
        for (int it = 0; it < 12; ++it) {
            int idx = tid + it * MLP_THREADS;
            if (idx < 4096) s4[idx] = w4[idx];
        }
    }
    {
#pragma unroll
        for (int it = 0; it < 8; ++it) {
            int idx = tid + it * MLP_THREADS;
            int r   = idx >> 5;
            int kq  = idx & 31;
            int rg  = row0 + r;
            float4 f = (rg < n) ? ((const float4*)A)[(size_t)rg * 32 + kq]
                                : make_float4(0.f, 0.f, 0.f, 0.f);
            *(float4*)&sA[r * SA_PITCH + kq * 4] = f;
        }
    }
    __syncthreads();

    const int trow = tid >> 5;
    const int tcol = tid & 31;
    const int r0   = trow * 8;
    const int c0   = tcol * 4;

    u64 acc[8][2];
    {
        u64 bb0 = pack2(g_b12[c0],     g_b12[c0 + 1]);
        u64 bb1 = pack2(g_b12[c0 + 2], g_b12[c0 + 3]);
#pragma unroll
        for (int i = 0; i < 8; ++i) { acc[i][0] = bb0; acc[i][1] = bb1; }
    }
#pragma unroll 1
    for (int k0 = 0; k0 < 128; k0 += 4) {
        float4 a4[8];
#pragma unroll
        for (int i = 0; i < 8; ++i)
            a4[i] = *(const float4*)&sA[(r0 + i) * SA_PITCH + k0];
#pragma unroll
        for (int kk = 0; kk < 4; ++kk) {
            ulonglong2 w = *(const ulonglong2*)&sW[(k0 + kk) * 128 + c0];
#pragma unroll
            for (int i = 0; i < 8; ++i) {
                float av = ((const float*)&a4[i])[kk];
                u64 aa = pack2(av, av);
                fma2(acc[i][0], aa, w.x);
                fma2(acc[i][1], aa, w.y);
            }
        }
    }

#pragma unroll
    for (int i = 0; i < 8; ++i) {
        int rg = row0 + r0 + i;
        if (rg < n) {
            float x0, y0, x1, y1;
            unpack2(acc[i][0], x0, y0);
            unpack2(acc[i][1], x1, y1);
            ((float4*)out)[(size_t)rg * 32 + tcol] = make_float4(x0, y0, x1, y1);
        }
    }
}

// ---------------------------- host ------------------------------------------

extern "C" void kernel_launch(void* const* d_in, const int* in_sizes, int n_in,
                              void* d_out, int out_size) {
    const float* feat = (const float*)d_in[0];
    const float* W1   = (const float*)d_in[1];
    const float* b1   = (const float*)d_in[2];
    const float* W2   = (const float*)d_in[3];
    const float* b2   = (const float*)d_in[4];
    const int*   src  = (const int*)d_in[5];
    const int*   dst  = (const int*)d_in[6];

    const int n = in_sizes[0] / DIM;
    const int e = in_sizes[5];

    cudaFuncSetAttribute((const void*)k_mlp,
                         cudaFuncAttributeMaxDynamicSharedMemorySize, MLP_SMEM_BYTES);
    cudaFuncSetAttribute((const void*)k_mlp1,
                         cudaFuncAttributeMaxDynamicSharedMemorySize, MLP_SMEM_BYTES);

    float *rst, *hA, *hB;
    cudaGetSymbolAddress((void**)&rst, g_rst);
    cudaGetSymbolAddress((void**)&hA,  g_hA);
    cudaGetSymbolAddress((void**)&hB,  g_hB);

    const int aggBlocks = (n + 7) / 8;                  // 8 warps / block
    const int mlpBlocks = (n + TILE_M - 1) / TILE_M;
    const int nb = (n + SCAN_CHUNK - 1) / SCAN_CHUNK;

    // ---- CSR build (g_deg zero at load; k_fill re-zeros for replay) ----
    k_hist<<<(e + 255) / 256, 256>>>(dst, e);                          // 0
    k_scan_reduce<<<nb, 256>>>(n);                                     // 1
    k_scan_final<<<nb, 256>>>(n, e, nb);                               // 2
    k_fill<<<(e + 255) / 256, 256>>>(src, dst, e, n);                  // 3
    k_wbfuse<<<129, 128>>>(W1 + 2 * DIM * DIM, W2 + 2 * DIM * DIM,
                           b1 + 2 * DIM, b2 + 2 * DIM);                // 4

    // ---- layer 0 ----
    k_agg<<<aggBlocks, 256>>>(feat, rst, n);                           // 5 (ncu)
    k_mlp<<<mlpBlocks, MLP_THREADS, MLP_SMEM_BYTES>>>(                 // 6
        rst, W1 + 0 * DIM * DIM, b1 + 0 * DIM, W2 + 0 * DIM * DIM, b2 + 0 * DIM,
        hA, n);
    // ---- layer 1 ----
    k_agg<<<aggBlocks, 256>>>(hA, rst, n);                             // 7
    k_mlp<<<mlpBlocks, MLP_THREADS, MLP_SMEM_BYTES>>>(                 // 8
        rst, W1 + 1 * DIM * DIM, b1 + 1 * DIM, W2 + 1 * DIM * DIM, b2 + 1 * DIM,
        hB, n);
    // ---- layer 2 (folded single GEMM, no relu) ----
    k_agg<<<aggBlocks, 256>>>(hB, rst, n);                             // 9
    k_mlp1<<<mlpBlocks, MLP_THREADS, MLP_SMEM_BYTES>>>(rst, (float*)d_out, n); // 10
}